// round 15
// baseline (speedup 1.0000x reference)
#include <cuda_runtime.h>
#include <cuda_fp16.h>
#include <math.h>
#include <stdint.h>

#define BATCH 8
#define NPTS 4096
#define SPTS 1024
#define D1 128
#define D2 256
#define INCH 384
#define OUTCH 256
#define NTOT (BATCH * NPTS)   // 32768
#define BN_EPS 1e-5f
#define WTOT (OUTCH * INCH + 2 * OUTCH * OUTCH)   // 229376
#define WSPLIT_BLOCKS 896     // ceil(WTOT/256)

// ---------------- scratch (device globals; no allocs allowed) ----------------
__device__ __align__(256) __half g_X[(size_t)NTOT * INCH];    // fp16 input, sample-major
__device__ __align__(256) __half g_A1[(size_t)NTOT * OUTCH];  // layer-fuse activation
__device__ __align__(256) __half g_A2[(size_t)NTOT * OUTCH];  // layer-1 activation
__device__ __align__(256) __half g_Z[(size_t)NTOT * OUTCH];   // pre-BN GEMM out (fp16)
__device__ __align__(256) __half g_W[WTOT];                   // fp16 weights (all 3 layers)
__device__ float g_w3[NTOT * 3];
__device__ int   g_i3[NTOT * 3];
__device__ float g_psum[3][OUTCH];   // per-layer BN partial sums (atomics, fp32-exact)
__device__ float g_psq[3][OUTCH];

// ---------------- helpers ----------------
__device__ __forceinline__ uint32_t smem_to_u32(const void* p) {
    uint32_t a;
    asm("{ .reg .u64 t; cvta.to.shared.u64 t, %1; cvt.u32.u64 %0, t; }" : "=r"(a) : "l"(p));
    return a;
}
#define SMZ(o) ((o) ^ (((o) >> 3) & 0x70))   // 128B-row swizzle
#define CP16(dst, src) \
    asm volatile("cp.async.cg.shared.global [%0], [%1], 16;" :: "r"(dst), "l"(src) : "memory")
template <int N>
__device__ __forceinline__ void cp_wait() {
    asm volatile("cp.async.wait_group %0;" :: "n"(N) : "memory");
}
__device__ __forceinline__ void ldsm_x4(uint32_t& r0, uint32_t& r1, uint32_t& r2, uint32_t& r3,
                                        uint32_t addr) {
    asm volatile("ldmatrix.sync.aligned.m8n8.x4.shared.b16 {%0,%1,%2,%3}, [%4];"
                 : "=r"(r0), "=r"(r1), "=r"(r2), "=r"(r3) : "r"(addr));
}
__device__ __forceinline__ void mma_fp16(float& c0, float& c1, float& c2, float& c3,
                                         uint32_t a0, uint32_t a1, uint32_t a2, uint32_t a3,
                                         uint32_t b0, uint32_t b1) {
    asm volatile("mma.sync.aligned.m16n8k16.row.col.f32.f16.f16.f32 "
                 "{%0,%1,%2,%3}, {%4,%5,%6,%7}, {%8,%9}, {%0,%1,%2,%3};"
                 : "+f"(c0), "+f"(c1), "+f"(c2), "+f"(c3)
                 : "r"(a0), "r"(a1), "r"(a2), "r"(a3), "r"(b0), "r"(b1));
}
__device__ __forceinline__ float gelu_exact(float x) {
    return 0.5f * x * (1.0f + erff(x * 0.70710678118654752f));
}

// ---------------- kernel 1: merged wsplit + topk ----------------
// blocks [0, 896): weight fp32->fp16 + zero stat accumulators
// blocks [896, 1024): per-sample top-3 neighbors (job = bid - 896)
__global__ __launch_bounds__(256) void prep_kernel(
    const float* __restrict__ Wf, const float* __restrict__ W1, const float* __restrict__ W2,
    const float* __restrict__ xyz1, const float* __restrict__ xyz2)
{
    __shared__ float4 q[SPTS];
    const int tid = threadIdx.x;

    if (blockIdx.x < WSPLIT_BLOCKS) {
        int i = blockIdx.x * 256 + tid;
        if (i < 3 * OUTCH) { (&g_psum[0][0])[i] = 0.0f; (&g_psq[0][0])[i] = 0.0f; }
        if (i >= WTOT) return;
        float w;
        if (i < OUTCH * INCH)                      w = Wf[i];
        else if (i < OUTCH * INCH + OUTCH * OUTCH) w = W1[i - OUTCH * INCH];
        else                                       w = W2[i - OUTCH * INCH - OUTCH * OUTCH];
        g_W[i] = __float2half_rn(w);
        return;
    }

    const int job = blockIdx.x - WSPLIT_BLOCKS;   // 0..127
    const int b = job >> 4;
    const int n = (job & 15) * 256 + tid;

    for (int s = tid; s < SPTS; s += 256) {
        const float* p = xyz2 + ((size_t)b * SPTS + s) * 3;
        float x = p[0], y = p[1], z = p[2];
        q[s] = make_float4(x, y, z, x * x + y * y + z * z);
    }
    __syncthreads();

    const float* p = xyz1 + ((size_t)b * NPTS + n) * 3;
    float px = p[0], py = p[1], pz = p[2];
    float rn = px * px + py * py + pz * pz;

    float d0 = 3.4e38f, d1 = 3.4e38f, d2 = 3.4e38f;
    int i0 = 0, i1 = 0, i2 = 0;
    #pragma unroll 4
    for (int s = 0; s < SPTS; s++) {
        float4 qq = q[s];
        float d = rn - 2.0f * (px * qq.x + py * qq.y + pz * qq.z) + qq.w;
        if (d < d2) {
            if (d < d1) {
                if (d < d0) { d2 = d1; i2 = i1; d1 = d0; i1 = i0; d0 = d; i0 = s; }
                else        { d2 = d1; i2 = i1; d1 = d;  i1 = s; }
            } else          { d2 = d;  i2 = s; }
        }
    }
    float r0 = 1.0f / (d0 + 1e-8f);
    float r1 = 1.0f / (d1 + 1e-8f);
    float r2 = 1.0f / (d2 + 1e-8f);
    float rs = 1.0f / (r0 + r1 + r2);
    const int sample = b * NPTS + n;
    g_w3[sample * 3 + 0] = r0 * rs;
    g_w3[sample * 3 + 1] = r1 * rs;
    g_w3[sample * 3 + 2] = r2 * rs;
    g_i3[sample * 3 + 0] = i0;
    g_i3[sample * 3 + 1] = i1;
    g_i3[sample * 3 + 2] = i2;
}

// ---------------- kernel 2: build fused input (fp16), sample-major ----------------
__global__ __launch_bounds__(384) void build_input(
    const float* __restrict__ points1, const float* __restrict__ points2)
{
    __shared__ float w[3];
    __shared__ int id[3];
    const int n = blockIdx.x;
    if (threadIdx.x < 3) {
        w[threadIdx.x]  = g_w3[n * 3 + threadIdx.x];
        id[threadIdx.x] = g_i3[n * 3 + threadIdx.x];
    }
    __syncthreads();
    const int c = threadIdx.x;
    float v;
    if (c < D1) {
        v = __ldg(points1 + (size_t)n * D1 + c);
    } else {
        const int b = n >> 12;
        const int cc = c - D1;
        const float* base = points2 + (size_t)b * SPTS * D2 + cc;
        v = w[0] * __ldg(base + (size_t)id[0] * D2)
          + w[1] * __ldg(base + (size_t)id[1] * D2)
          + w[2] * __ldg(base + (size_t)id[2] * D2);
    }
    g_X[(size_t)n * INCH + c] = __float2half_rn(v);
}

// 128 rows x 64 fp16 (128B/row) tile = 16KB; 4 CP16/thread.
__device__ __forceinline__ void load_tile64(uint32_t dst, const __half* src,
                                            int ldK, int row0, int k0, int tid) {
    #pragma unroll
    for (int j = 0; j < 4; j++) {
        int g = tid + j * 256;
        int r = g >> 3;
        int c16 = (g & 7) * 16;
        const char* s = (const char*)(src + (size_t)(row0 + r) * ldK + k0) + c16;
        CP16(dst + SMZ(r * 128 + c16), s);
    }
}

// shared epilogue: bias, fp16 Z write, fused fp32-exact BN sums
__device__ __forceinline__ void gemm_epilogue(
    float acc[4][4][4], const float* sbias, int sample0, int n0,
    int mWarp, int nWarp, int lane, int layer)
{
    const int rr = lane >> 2;
    const int cc = (lane & 3) * 2;
    #pragma unroll
    for (int nb = 0; nb < 4; nb++) {
        const int col = nWarp + nb * 8 + cc;
        const float b0 = sbias[col], b1 = sbias[col + 1];
        float cs0 = 0.0f, cs1 = 0.0f, cq0 = 0.0f, cq1 = 0.0f;
        #pragma unroll
        for (int mb = 0; mb < 4; mb++) {
            const int row0 = sample0 + mWarp + mb * 16 + rr;
            float v00 = acc[mb][nb][0] + b0;
            float v01 = acc[mb][nb][1] + b1;
            float v10 = acc[mb][nb][2] + b0;
            float v11 = acc[mb][nb][3] + b1;
            __half2 z0 = __floats2half2_rn(v00, v01);
            __half2 z1 = __floats2half2_rn(v10, v11);
            *(__half2*)(g_Z + (size_t)row0 * OUTCH + n0 + col)       = z0;
            *(__half2*)(g_Z + (size_t)(row0 + 8) * OUTCH + n0 + col) = z1;
            cs0 += v00 + v10;
            cs1 += v01 + v11;
            cq0 += v00 * v00 + v10 * v10;
            cq1 += v01 * v01 + v11 * v11;
        }
        #pragma unroll
        for (int off = 4; off <= 16; off <<= 1) {
            cs0 += __shfl_xor_sync(0xFFFFFFFF, cs0, off);
            cs1 += __shfl_xor_sync(0xFFFFFFFF, cs1, off);
            cq0 += __shfl_xor_sync(0xFFFFFFFF, cq0, off);
            cq1 += __shfl_xor_sync(0xFFFFFFFF, cq1, off);
        }
        if (lane < 4) {
            atomicAdd(&g_psum[layer][n0 + col],     cs0);
            atomicAdd(&g_psum[layer][n0 + col + 1], cs1);
            atomicAdd(&g_psq[layer][n0 + col],      cq0);
            atomicAdd(&g_psq[layer][n0 + col + 1],  cq1);
        }
    }
}

// compute one BK=64 chunk: A frags from sA, B frags from sB
__device__ __forceinline__ void compute_chunk64(
    uint32_t sA, uint32_t sB, float acc[4][4][4],
    int aRow, int aColHalf, int bRow, int bColHalf)
{
    #pragma unroll
    for (int k16 = 0; k16 < 4; k16++) {
        uint32_t af[4][4];
        #pragma unroll
        for (int mb = 0; mb < 4; mb++) {
            uint32_t addr = sA + SMZ((aRow + mb * 16) * 128 + k16 * 32 + aColHalf);
            ldsm_x4(af[mb][0], af[mb][1], af[mb][2], af[mb][3], addr);
        }
        uint32_t bf[2][4];
        #pragma unroll
        for (int p = 0; p < 2; p++) {
            uint32_t addr = sB + SMZ((bRow + p * 16) * 128 + k16 * 32 + bColHalf);
            ldsm_x4(bf[p][0], bf[p][1], bf[p][2], bf[p][3], addr);
        }
        #pragma unroll
        for (int mb = 0; mb < 4; mb++)
            #pragma unroll
            for (int nb = 0; nb < 4; nb++) {
                uint32_t b0 = bf[nb >> 1][(nb & 1) * 2];
                uint32_t b1 = bf[nb >> 1][(nb & 1) * 2 + 1];
                mma_fp16(acc[mb][nb][0], acc[mb][nb][1], acc[mb][nb][2], acc[mb][nb][3],
                         af[mb][0], af[mb][1], af[mb][2], af[mb][3], b0, b1);
            }
    }
}

// ---------------- GEMM variant A: K=384, streamed W (R14 structure) ----------------
#define STAGE_SZ 32768
#define NSTAGE 3
#define GEMM_SMEM (NSTAGE * STAGE_SZ + 512)

__global__ __launch_bounds__(256, 2) void gemm_k384(
    const __half* __restrict__ X, const float* __restrict__ bias)
{
    constexpr int K = INCH, NC = K / 64;   // 6
    extern __shared__ char smem[];
    const uint32_t sb = smem_to_u32(smem);
    const int tid = threadIdx.x;
    const int wid = tid >> 5;
    const int lane = tid & 31;
    const int sample0 = blockIdx.x * 128;
    const int n0 = blockIdx.y * 128;

    const int mWarp = (wid & 1) * 64;
    const int nWarp = (wid >> 1) * 32;

    if (tid < 128) ((float*)(smem + NSTAGE * STAGE_SZ))[tid] = bias[n0 + tid];

    const __half* W = g_W;   // layer 0 at offset 0

    #pragma unroll
    for (int i = 0; i < NSTAGE; i++) {
        const uint32_t st = sb + i * STAGE_SZ;
        load_tile64(st,         X, K, sample0, i * 64, tid);
        load_tile64(st + 16384, W, K, n0,      i * 64, tid);
        asm volatile("cp.async.commit_group;" ::: "memory");
    }

    float acc[4][4][4];
    #pragma unroll
    for (int a = 0; a < 4; a++)
        #pragma unroll
        for (int b2 = 0; b2 < 4; b2++)
            #pragma unroll
            for (int c = 0; c < 4; c++) acc[a][b2][c] = 0.0f;

    const int aRow = mWarp + (lane & 15);
    const int aColHalf = (lane >> 4) * 16;
    const int bRow = nWarp + ((lane >> 4) << 3) + (lane & 7);
    const int bColHalf = ((lane >> 3) & 1) * 16;

    int stage = 0;
    for (int i = 0; i < NC; i++) {
        if (i <= NC - 3)      cp_wait<2>();
        else if (i == NC - 2) cp_wait<1>();
        else                  cp_wait<0>();
        __syncthreads();

        const uint32_t sA = sb + stage * STAGE_SZ;
        compute_chunk64(sA, sA + 16384, acc, aRow, aColHalf, bRow, bColHalf);
        __syncthreads();

        if (i + NSTAGE < NC) {
            const int j = i + NSTAGE;
            const uint32_t st = sb + stage * STAGE_SZ;
            load_tile64(st,         X, K, sample0, j * 64, tid);
            load_tile64(st + 16384, W, K, n0,      j * 64, tid);
            asm volatile("cp.async.commit_group;" ::: "memory");
        }
        stage = (stage + 1 == NSTAGE) ? 0 : stage + 1;
    }

    gemm_epilogue(acc, (const float*)(smem + NSTAGE * STAGE_SZ),
                  sample0, n0, mWarp, nWarp, lane, 0);
}

// ---------------- GEMM variant B: K=256, W fully resident in SMEM ----------------
// smem: X stages [0, 3*16KB) | W [48KB, 112KB) | bias [112KB, +512)
#define XSTG 16384
#define WOFF_S (3 * XSTG)            // 49152
#define BIAS_S (WOFF_S + 65536)      // 114688
#define WRES_SMEM (BIAS_S + 512)     // 115200 (112.5 KB)

__global__ __launch_bounds__(256, 2) void gemm_wres(
    const __half* __restrict__ X, const float* __restrict__ bias, int woff, int layer)
{
    constexpr int K = OUTCH, NC = K / 64;   // 4
    extern __shared__ char smem[];
    const uint32_t sb = smem_to_u32(smem);
    const int tid = threadIdx.x;
    const int wid = tid >> 5;
    const int lane = tid & 31;
    const int sample0 = blockIdx.x * 128;
    const int n0 = blockIdx.y * 128;

    const int mWarp = (wid & 1) * 64;
    const int nWarp = (wid >> 1) * 32;

    if (tid < 128) ((float*)(smem + BIAS_S))[tid] = bias[n0 + tid];

    const __half* W = g_W + woff;

    // group 0: ALL of W (4 chunk tiles)
    #pragma unroll
    for (int c = 0; c < 4; c++)
        load_tile64(sb + WOFF_S + c * XSTG, W, K, n0, c * 64, tid);
    asm volatile("cp.async.commit_group;" ::: "memory");
    // groups 1..3: X chunks 0..2
    #pragma unroll
    for (int i = 0; i < 3; i++) {
        load_tile64(sb + i * XSTG, X, K, sample0, i * 64, tid);
        asm volatile("cp.async.commit_group;" ::: "memory");
    }

    float acc[4][4][4];
    #pragma unroll
    for (int a = 0; a < 4; a++)
        #pragma unroll
        for (int b2 = 0; b2 < 4; b2++)
            #pragma unroll
            for (int c = 0; c < 4; c++) acc[a][b2][c] = 0.0f;

    const int aRow = mWarp + (lane & 15);
    const int aColHalf = (lane >> 4) * 16;
    const int bRow = nWarp + ((lane >> 4) << 3) + (lane & 7);
    const int bColHalf = ((lane >> 3) & 1) * 16;

    int stage = 0;
    for (int i = 0; i < NC; i++) {
        if (i <= NC - 3)      cp_wait<2>();    // oldest groups (incl. W) complete
        else if (i == NC - 2) cp_wait<1>();
        else                  cp_wait<0>();
        __syncthreads();

        compute_chunk64(sb + stage * XSTG, sb + WOFF_S + i * XSTG,
                        acc, aRow, aColHalf, bRow, bColHalf);

        if (i + 3 < NC) {     // only i == 0
            __syncthreads();
            load_tile64(sb + stage * XSTG, X, K, sample0, (i + 3) * 64, tid);
            asm volatile("cp.async.commit_group;" ::: "memory");
        }
        stage = (stage + 1 == 3) ? 0 : stage + 1;
    }

    gemm_epilogue(acc, (const float*)(smem + BIAS_S),
                  sample0, n0, mWarp, nWarp, lane, layer);
}

// ---------------- BN(+stats finalize) + GELU: fp16 Z -> fp16 activation ----------------
__global__ __launch_bounds__(256) void bn_act(
    __half* __restrict__ A, const float* __restrict__ gamma, const float* __restrict__ beta,
    int layer)
{
    __shared__ float s_sc[OUTCH], s_sh[OUTCH];
    const int t = threadIdx.x;
    {
        float s = g_psum[layer][t];
        float q = g_psq[layer][t];
        float m = s * (1.0f / NTOT);
        float var = q * (1.0f / NTOT) - m * m;
        float r = rsqrtf(var + BN_EPS);
        float sc = r * __ldg(gamma + t);
        s_sc[t] = sc;
        s_sh[t] = __ldg(beta + t) - m * sc;
    }
    __syncthreads();

    const int idx4 = blockIdx.x * 256 + t;
    const int c4 = (idx4 & 63) * 4;
    uint2 zv = ((const uint2*)g_Z)[idx4];
    __half2 z01 = *reinterpret_cast<__half2*>(&zv.x);
    __half2 z23 = *reinterpret_cast<__half2*>(&zv.y);
    __half2 h01, h23;
    h01.x = __float2half_rn(gelu_exact(fmaf(__half2float(z01.x), s_sc[c4 + 0], s_sh[c4 + 0])));
    h01.y = __float2half_rn(gelu_exact(fmaf(__half2float(z01.y), s_sc[c4 + 1], s_sh[c4 + 1])));
    h23.x = __float2half_rn(gelu_exact(fmaf(__half2float(z23.x), s_sc[c4 + 2], s_sh[c4 + 2])));
    h23.y = __float2half_rn(gelu_exact(fmaf(__half2float(z23.y), s_sc[c4 + 3], s_sh[c4 + 3])));
    uint2 v;
    v.x = *reinterpret_cast<uint32_t*>(&h01);
    v.y = *reinterpret_cast<uint32_t*>(&h23);
    ((uint2*)A)[idx4] = v;
}

// ---------------- final: BN(+stats) + residual + GELU -> fp32 out ----------------
__global__ __launch_bounds__(256) void final_k(
    float* __restrict__ out, const float* __restrict__ gamma, const float* __restrict__ beta)
{
    __shared__ float s_sc[OUTCH], s_sh[OUTCH];
    const int t = threadIdx.x;
    {
        float s = g_psum[2][t];
        float q = g_psq[2][t];
        float m = s * (1.0f / NTOT);
        float var = q * (1.0f / NTOT) - m * m;
        float r = rsqrtf(var + BN_EPS);
        float sc = r * __ldg(gamma + t);
        s_sc[t] = sc;
        s_sh[t] = __ldg(beta + t) - m * sc;
    }
    __syncthreads();

    const int idx4 = blockIdx.x * 256 + t;
    const int c4 = (idx4 & 63) * 4;
    uint2 zv = ((const uint2*)g_Z)[idx4];
    __half2 z01 = *reinterpret_cast<__half2*>(&zv.x);
    __half2 z23 = *reinterpret_cast<__half2*>(&zv.y);
    uint2 rv = ((const uint2*)g_A1)[idx4];
    __half2 r01 = *reinterpret_cast<__half2*>(&rv.x);
    __half2 r23 = *reinterpret_cast<__half2*>(&rv.y);
    float4 o;
    o.x = gelu_exact(fmaf(__half2float(z01.x), s_sc[c4 + 0], s_sh[c4 + 0]) + __half2float(r01.x));
    o.y = gelu_exact(fmaf(__half2float(z01.y), s_sc[c4 + 1], s_sh[c4 + 1]) + __half2float(r01.y));
    o.z = gelu_exact(fmaf(__half2float(z23.x), s_sc[c4 + 2], s_sh[c4 + 2]) + __half2float(r23.x));
    o.w = gelu_exact(fmaf(__half2float(z23.y), s_sc[c4 + 3], s_sh[c4 + 3]) + __half2float(r23.y));
    ((float4*)out)[idx4] = o;
}

// ---------------- launch ----------------
extern "C" void kernel_launch(void* const* d_in, const int* in_sizes, int n_in,
                              void* d_out, int out_size) {
    const float* xyz1    = (const float*)d_in[0];
    const float* xyz2    = (const float*)d_in[1];
    const float* points1 = (const float*)d_in[2];
    const float* points2 = (const float*)d_in[3];
    const float* W_fuse  = (const float*)d_in[4];
    const float* b_fuse  = (const float*)d_in[5];
    const float* g_fuse  = (const float*)d_in[6];
    const float* bt_fuse = (const float*)d_in[7];
    const float* W1      = (const float*)d_in[8];
    const float* b1      = (const float*)d_in[9];
    const float* g1      = (const float*)d_in[10];
    const float* bt1     = (const float*)d_in[11];
    const float* W2      = (const float*)d_in[12];
    const float* b2      = (const float*)d_in[13];
    const float* g2      = (const float*)d_in[14];
    const float* bt2     = (const float*)d_in[15];
    float* out = (float*)d_out;

    __half *pX, *pA1, *pA2;
    cudaGetSymbolAddress((void**)&pX,  g_X);
    cudaGetSymbolAddress((void**)&pA1, g_A1);
    cudaGetSymbolAddress((void**)&pA2, g_A2);

    cudaFuncSetAttribute(gemm_k384, cudaFuncAttributeMaxDynamicSharedMemorySize, GEMM_SMEM);
    cudaFuncSetAttribute(gemm_wres, cudaFuncAttributeMaxDynamicSharedMemorySize, WRES_SMEM);

    const dim3 gemm_grid(NTOT / 128, OUTCH / 128);
    const int bn_blocks = (OUTCH * NTOT / 4) / 256;   // 8192

    prep_kernel<<<WSPLIT_BLOCKS + 128, 256>>>(W_fuse, W1, W2, xyz1, xyz2);
    build_input<<<NTOT, 384>>>(points1, points2);

    const int woff_1 = OUTCH * INCH;
    const int woff_2 = OUTCH * INCH + OUTCH * OUTCH;

    // layer fuse (K=384, streamed W)
    gemm_k384<<<gemm_grid, 256, GEMM_SMEM>>>(pX, b_fuse);
    bn_act<<<bn_blocks, 256>>>(pA1, g_fuse, bt_fuse, 0);

    // layer 1 (K=256, W-resident)
    gemm_wres<<<gemm_grid, 256, WRES_SMEM>>>(pA1, b1, woff_1, 1);
    bn_act<<<bn_blocks, 256>>>(pA2, g1, bt1, 1);

    // layer 2 (K=256, W-resident) + residual + output
    gemm_wres<<<gemm_grid, 256, WRES_SMEM>>>(pA2, b2, woff_2, 2);
    final_k<<<bn_blocks, 256>>>(out, g2, bt2);
}

// round 16
// speedup vs baseline: 1.4677x; 1.4677x over previous
#include <cuda_runtime.h>
#include <cuda_fp16.h>
#include <math.h>
#include <stdint.h>

#define BATCH 8
#define NPTS 4096
#define SPTS 1024
#define D1 128
#define D2 256
#define INCH 384
#define OUTCH 256
#define NTOT (BATCH * NPTS)   // 32768
#define BN_EPS 1e-5f
#define WTOT (OUTCH * INCH + 2 * OUTCH * OUTCH)   // 229376
#define WSPLIT_BLOCKS 896     // ceil(WTOT/256)

// ---------------- scratch (device globals; no allocs allowed) ----------------
__device__ __align__(256) __half g_X[(size_t)NTOT * INCH];    // fp16 input, sample-major
__device__ __align__(256) __half g_A1[(size_t)NTOT * OUTCH];  // layer-fuse activation
__device__ __align__(256) __half g_A2[(size_t)NTOT * OUTCH];  // layer-1 activation
__device__ __align__(256) __half g_Z[(size_t)NTOT * OUTCH];   // pre-BN GEMM out (fp16)
__device__ __align__(256) __half g_W[WTOT];                   // fp16 weights (all 3 layers)
__device__ float g_w3[NTOT * 3];
__device__ int   g_i3[NTOT * 3];
__device__ float g_psum[3][OUTCH];   // per-layer BN partial sums (atomics, fp32-exact)
__device__ float g_psq[3][OUTCH];

// ---------------- helpers ----------------
__device__ __forceinline__ uint32_t smem_to_u32(const void* p) {
    uint32_t a;
    asm("{ .reg .u64 t; cvta.to.shared.u64 t, %1; cvt.u32.u64 %0, t; }" : "=r"(a) : "l"(p));
    return a;
}
#define SMZ(o) ((o) ^ (((o) >> 3) & 0x70))   // 128B-row swizzle
#define CP16(dst, src) \
    asm volatile("cp.async.cg.shared.global [%0], [%1], 16;" :: "r"(dst), "l"(src) : "memory")
template <int N>
__device__ __forceinline__ void cp_wait() {
    asm volatile("cp.async.wait_group %0;" :: "n"(N) : "memory");
}
__device__ __forceinline__ void ldsm_x4(uint32_t& r0, uint32_t& r1, uint32_t& r2, uint32_t& r3,
                                        uint32_t addr) {
    asm volatile("ldmatrix.sync.aligned.m8n8.x4.shared.b16 {%0,%1,%2,%3}, [%4];"
                 : "=r"(r0), "=r"(r1), "=r"(r2), "=r"(r3) : "r"(addr));
}
__device__ __forceinline__ void mma_fp16(float& c0, float& c1, float& c2, float& c3,
                                         uint32_t a0, uint32_t a1, uint32_t a2, uint32_t a3,
                                         uint32_t b0, uint32_t b1) {
    asm volatile("mma.sync.aligned.m16n8k16.row.col.f32.f16.f16.f32 "
                 "{%0,%1,%2,%3}, {%4,%5,%6,%7}, {%8,%9}, {%0,%1,%2,%3};"
                 : "+f"(c0), "+f"(c1), "+f"(c2), "+f"(c3)
                 : "r"(a0), "r"(a1), "r"(a2), "r"(a3), "r"(b0), "r"(b1));
}
__device__ __forceinline__ float gelu_exact(float x) {
    return 0.5f * x * (1.0f + erff(x * 0.70710678118654752f));
}

// ---------------- kernel 1: merged wsplit + topk ----------------
// blocks [0, 896): weight fp32->fp16 + zero stat accumulators
// blocks [896, 1024): per-sample top-3 neighbors (job = bid - 896)
__global__ __launch_bounds__(256) void prep_kernel(
    const float* __restrict__ Wf, const float* __restrict__ W1, const float* __restrict__ W2,
    const float* __restrict__ xyz1, const float* __restrict__ xyz2)
{
    __shared__ float4 q[SPTS];
    const int tid = threadIdx.x;

    if (blockIdx.x < WSPLIT_BLOCKS) {
        int i = blockIdx.x * 256 + tid;
        if (i < 3 * OUTCH) { (&g_psum[0][0])[i] = 0.0f; (&g_psq[0][0])[i] = 0.0f; }
        if (i >= WTOT) return;
        float w;
        if (i < OUTCH * INCH)                      w = Wf[i];
        else if (i < OUTCH * INCH + OUTCH * OUTCH) w = W1[i - OUTCH * INCH];
        else                                       w = W2[i - OUTCH * INCH - OUTCH * OUTCH];
        g_W[i] = __float2half_rn(w);
        return;
    }

    const int job = blockIdx.x - WSPLIT_BLOCKS;   // 0..127
    const int b = job >> 4;
    const int n = (job & 15) * 256 + tid;

    for (int s = tid; s < SPTS; s += 256) {
        const float* p = xyz2 + ((size_t)b * SPTS + s) * 3;
        float x = p[0], y = p[1], z = p[2];
        q[s] = make_float4(x, y, z, x * x + y * y + z * z);
    }
    __syncthreads();

    const float* p = xyz1 + ((size_t)b * NPTS + n) * 3;
    float px = p[0], py = p[1], pz = p[2];
    float rn = px * px + py * py + pz * pz;

    float d0 = 3.4e38f, d1 = 3.4e38f, d2 = 3.4e38f;
    int i0 = 0, i1 = 0, i2 = 0;
    #pragma unroll 4
    for (int s = 0; s < SPTS; s++) {
        float4 qq = q[s];
        float d = rn - 2.0f * (px * qq.x + py * qq.y + pz * qq.z) + qq.w;
        if (d < d2) {
            if (d < d1) {
                if (d < d0) { d2 = d1; i2 = i1; d1 = d0; i1 = i0; d0 = d; i0 = s; }
                else        { d2 = d1; i2 = i1; d1 = d;  i1 = s; }
            } else          { d2 = d;  i2 = s; }
        }
    }
    float r0 = 1.0f / (d0 + 1e-8f);
    float r1 = 1.0f / (d1 + 1e-8f);
    float r2 = 1.0f / (d2 + 1e-8f);
    float rs = 1.0f / (r0 + r1 + r2);
    const int sample = b * NPTS + n;
    g_w3[sample * 3 + 0] = r0 * rs;
    g_w3[sample * 3 + 1] = r1 * rs;
    g_w3[sample * 3 + 2] = r2 * rs;
    g_i3[sample * 3 + 0] = i0;
    g_i3[sample * 3 + 1] = i1;
    g_i3[sample * 3 + 2] = i2;
}

// ---------------- kernel 2: build fused input (fp16), sample-major ----------------
__global__ __launch_bounds__(384) void build_input(
    const float* __restrict__ points1, const float* __restrict__ points2)
{
    __shared__ float w[3];
    __shared__ int id[3];
    const int n = blockIdx.x;
    if (threadIdx.x < 3) {
        w[threadIdx.x]  = g_w3[n * 3 + threadIdx.x];
        id[threadIdx.x] = g_i3[n * 3 + threadIdx.x];
    }
    __syncthreads();
    const int c = threadIdx.x;
    float v;
    if (c < D1) {
        v = __ldg(points1 + (size_t)n * D1 + c);
    } else {
        const int b = n >> 12;
        const int cc = c - D1;
        const float* base = points2 + (size_t)b * SPTS * D2 + cc;
        v = w[0] * __ldg(base + (size_t)id[0] * D2)
          + w[1] * __ldg(base + (size_t)id[1] * D2)
          + w[2] * __ldg(base + (size_t)id[2] * D2);
    }
    g_X[(size_t)n * INCH + c] = __float2half_rn(v);
}

// ---------------- GEMM: single-pass fp16, BK=64 (R13/R14 structure), fp16 Z out ----------------
// CTA 128x128, BK=64, 3-stage cp.async pipeline, 2 barriers/chunk.
// Stage = A(16KB) + W(16KB) = 32KB; 128B rows, SW128 swizzle.
#define STAGE_SZ 32768
#define NSTAGE 3
#define GEMM_SMEM (NSTAGE * STAGE_SZ + 512)

// 128 rows x 64 fp16 (128B/row) tile = 16KB; 4 CP16/thread.
__device__ __forceinline__ void load_tile64(uint32_t dst, const __half* src,
                                            int ldK, int row0, int k0, int tid) {
    #pragma unroll
    for (int j = 0; j < 4; j++) {
        int g = tid + j * 256;
        int r = g >> 3;
        int c16 = (g & 7) * 16;
        const char* s = (const char*)(src + (size_t)(row0 + r) * ldK + k0) + c16;
        CP16(dst + SMZ(r * 128 + c16), s);
    }
}

template <int K>
__global__ __launch_bounds__(256, 2) void gemm_mma(
    const __half* __restrict__ X, const float* __restrict__ bias, int woff, int layer)
{
    constexpr int NC = K / 64;       // chunks (6 or 4)
    extern __shared__ char smem[];
    const uint32_t sb = smem_to_u32(smem);
    const int tid = threadIdx.x;
    const int wid = tid >> 5;
    const int lane = tid & 31;
    const int sample0 = blockIdx.x * 128;
    const int n0 = blockIdx.y * 128;

    const int mWarp = (wid & 1) * 64;
    const int nWarp = (wid >> 1) * 32;

    if (tid < 128) ((float*)(smem + NSTAGE * STAGE_SZ))[tid] = bias[n0 + tid];

    const __half* W = g_W + woff;

    // prologue: chunks 0,1,2 into stages 0,1,2
    #pragma unroll
    for (int i = 0; i < NSTAGE; i++) {
        const uint32_t st = sb + i * STAGE_SZ;
        load_tile64(st,         X, K, sample0, i * 64, tid);
        load_tile64(st + 16384, W, K, n0,      i * 64, tid);
        asm volatile("cp.async.commit_group;" ::: "memory");
    }

    float acc[4][4][4];
    #pragma unroll
    for (int a = 0; a < 4; a++)
        #pragma unroll
        for (int b2 = 0; b2 < 4; b2++)
            #pragma unroll
            for (int c = 0; c < 4; c++) acc[a][b2][c] = 0.0f;

    const int aRow = mWarp + (lane & 15);
    const int aColHalf = (lane >> 4) * 16;             // bytes
    const int bRow = nWarp + ((lane >> 4) << 3) + (lane & 7);
    const int bColHalf = ((lane >> 3) & 1) * 16;       // bytes

    int stage = 0;
    for (int i = 0; i < NC; i++) {
        if (i <= NC - 3)      cp_wait<2>();
        else if (i == NC - 2) cp_wait<1>();
        else                  cp_wait<0>();
        __syncthreads();

        const uint32_t sA = sb + stage * STAGE_SZ;
        const uint32_t sB = sA + 16384;

        #pragma unroll
        for (int k16 = 0; k16 < 4; k16++) {
            uint32_t af[4][4];
            #pragma unroll
            for (int mb = 0; mb < 4; mb++) {
                uint32_t addr = sA + SMZ((aRow + mb * 16) * 128 + k16 * 32 + aColHalf);
                ldsm_x4(af[mb][0], af[mb][1], af[mb][2], af[mb][3], addr);
            }
            uint32_t bf[2][4];
            #pragma unroll
            for (int p = 0; p < 2; p++) {
                uint32_t addr = sB + SMZ((bRow + p * 16) * 128 + k16 * 32 + bColHalf);
                ldsm_x4(bf[p][0], bf[p][1], bf[p][2], bf[p][3], addr);
            }
            #pragma unroll
            for (int mb = 0; mb < 4; mb++)
                #pragma unroll
                for (int nb = 0; nb < 4; nb++) {
                    uint32_t b0 = bf[nb >> 1][(nb & 1) * 2];
                    uint32_t b1 = bf[nb >> 1][(nb & 1) * 2 + 1];
                    mma_fp16(acc[mb][nb][0], acc[mb][nb][1], acc[mb][nb][2], acc[mb][nb][3],
                             af[mb][0], af[mb][1], af[mb][2], af[mb][3], b0, b1);
                }
        }
        __syncthreads();

        if (i + NSTAGE < NC) {
            const int j = i + NSTAGE;
            const uint32_t st = sb + stage * STAGE_SZ;   // (i+3)%3 == i%3
            load_tile64(st,         X, K, sample0, j * 64, tid);
            load_tile64(st + 16384, W, K, n0,      j * 64, tid);
            asm volatile("cp.async.commit_group;" ::: "memory");
        }
        stage = (stage + 1 == NSTAGE) ? 0 : stage + 1;
    }

    // epilogue: bias, write fp16 Z (sample-major), fused fp32-exact BN sums
    const float* sbias = (const float*)(smem + NSTAGE * STAGE_SZ);
    const int rr = lane >> 2;
    const int cc = (lane & 3) * 2;
    #pragma unroll
    for (int nb = 0; nb < 4; nb++) {
        const int col = nWarp + nb * 8 + cc;
        const float b0 = sbias[col], b1 = sbias[col + 1];
        float cs0 = 0.0f, cs1 = 0.0f, cq0 = 0.0f, cq1 = 0.0f;
        #pragma unroll
        for (int mb = 0; mb < 4; mb++) {
            const int row0 = sample0 + mWarp + mb * 16 + rr;
            float v00 = acc[mb][nb][0] + b0;
            float v01 = acc[mb][nb][1] + b1;
            float v10 = acc[mb][nb][2] + b0;
            float v11 = acc[mb][nb][3] + b1;
            __half2 z0 = __floats2half2_rn(v00, v01);
            __half2 z1 = __floats2half2_rn(v10, v11);
            *(__half2*)(g_Z + (size_t)row0 * OUTCH + n0 + col)       = z0;
            *(__half2*)(g_Z + (size_t)(row0 + 8) * OUTCH + n0 + col) = z1;
            cs0 += v00 + v10;
            cs1 += v01 + v11;
            cq0 += v00 * v00 + v10 * v10;
            cq1 += v01 * v01 + v11 * v11;
        }
        #pragma unroll
        for (int off = 4; off <= 16; off <<= 1) {
            cs0 += __shfl_xor_sync(0xFFFFFFFF, cs0, off);
            cs1 += __shfl_xor_sync(0xFFFFFFFF, cs1, off);
            cq0 += __shfl_xor_sync(0xFFFFFFFF, cq0, off);
            cq1 += __shfl_xor_sync(0xFFFFFFFF, cq1, off);
        }
        if (lane < 4) {
            atomicAdd(&g_psum[layer][n0 + col],     cs0);
            atomicAdd(&g_psum[layer][n0 + col + 1], cs1);
            atomicAdd(&g_psq[layer][n0 + col],      cq0);
            atomicAdd(&g_psq[layer][n0 + col + 1],  cq1);
        }
    }
}

// ---------------- BN(+stats finalize) + GELU: fp16 Z -> fp16 activation ----------------
__global__ __launch_bounds__(256) void bn_act(
    __half* __restrict__ A, const float* __restrict__ gamma, const float* __restrict__ beta,
    int layer)
{
    __shared__ float s_sc[OUTCH], s_sh[OUTCH];
    const int t = threadIdx.x;
    {
        float s = g_psum[layer][t];
        float q = g_psq[layer][t];
        float m = s * (1.0f / NTOT);
        float var = q * (1.0f / NTOT) - m * m;
        float r = rsqrtf(var + BN_EPS);
        float sc = r * __ldg(gamma + t);
        s_sc[t] = sc;
        s_sh[t] = __ldg(beta + t) - m * sc;
    }
    __syncthreads();

    const int idx4 = blockIdx.x * 256 + t;       // group of 4 elements
    const int c4 = (idx4 & 63) * 4;
    uint2 zv = ((const uint2*)g_Z)[idx4];
    __half2 z01 = *reinterpret_cast<__half2*>(&zv.x);
    __half2 z23 = *reinterpret_cast<__half2*>(&zv.y);
    __half2 h01, h23;
    h01.x = __float2half_rn(gelu_exact(fmaf(__half2float(z01.x), s_sc[c4 + 0], s_sh[c4 + 0])));
    h01.y = __float2half_rn(gelu_exact(fmaf(__half2float(z01.y), s_sc[c4 + 1], s_sh[c4 + 1])));
    h23.x = __float2half_rn(gelu_exact(fmaf(__half2float(z23.x), s_sc[c4 + 2], s_sh[c4 + 2])));
    h23.y = __float2half_rn(gelu_exact(fmaf(__half2float(z23.y), s_sc[c4 + 3], s_sh[c4 + 3])));
    uint2 v;
    v.x = *reinterpret_cast<uint32_t*>(&h01);
    v.y = *reinterpret_cast<uint32_t*>(&h23);
    ((uint2*)A)[idx4] = v;
}

// ---------------- final: BN(+stats) + residual + GELU -> fp32 out ----------------
__global__ __launch_bounds__(256) void final_k(
    float* __restrict__ out, const float* __restrict__ gamma, const float* __restrict__ beta)
{
    __shared__ float s_sc[OUTCH], s_sh[OUTCH];
    const int t = threadIdx.x;
    {
        float s = g_psum[2][t];
        float q = g_psq[2][t];
        float m = s * (1.0f / NTOT);
        float var = q * (1.0f / NTOT) - m * m;
        float r = rsqrtf(var + BN_EPS);
        float sc = r * __ldg(gamma + t);
        s_sc[t] = sc;
        s_sh[t] = __ldg(beta + t) - m * sc;
    }
    __syncthreads();

    const int idx4 = blockIdx.x * 256 + t;
    const int c4 = (idx4 & 63) * 4;
    uint2 zv = ((const uint2*)g_Z)[idx4];
    __half2 z01 = *reinterpret_cast<__half2*>(&zv.x);
    __half2 z23 = *reinterpret_cast<__half2*>(&zv.y);
    uint2 rv = ((const uint2*)g_A1)[idx4];
    __half2 r01 = *reinterpret_cast<__half2*>(&rv.x);
    __half2 r23 = *reinterpret_cast<__half2*>(&rv.y);
    float4 o;
    o.x = gelu_exact(fmaf(__half2float(z01.x), s_sc[c4 + 0], s_sh[c4 + 0]) + __half2float(r01.x));
    o.y = gelu_exact(fmaf(__half2float(z01.y), s_sc[c4 + 1], s_sh[c4 + 1]) + __half2float(r01.y));
    o.z = gelu_exact(fmaf(__half2float(z23.x), s_sc[c4 + 2], s_sh[c4 + 2]) + __half2float(r23.x));
    o.w = gelu_exact(fmaf(__half2float(z23.y), s_sc[c4 + 3], s_sh[c4 + 3]) + __half2float(r23.y));
    ((float4*)out)[idx4] = o;
}

// ---------------- launch ----------------
extern "C" void kernel_launch(void* const* d_in, const int* in_sizes, int n_in,
                              void* d_out, int out_size) {
    const float* xyz1    = (const float*)d_in[0];
    const float* xyz2    = (const float*)d_in[1];
    const float* points1 = (const float*)d_in[2];
    const float* points2 = (const float*)d_in[3];
    const float* W_fuse  = (const float*)d_in[4];
    const float* b_fuse  = (const float*)d_in[5];
    const float* g_fuse  = (const float*)d_in[6];
    const float* bt_fuse = (const float*)d_in[7];
    const float* W1      = (const float*)d_in[8];
    const float* b1      = (const float*)d_in[9];
    const float* g1      = (const float*)d_in[10];
    const float* bt1     = (const float*)d_in[11];
    const float* W2      = (const float*)d_in[12];
    const float* b2      = (const float*)d_in[13];
    const float* g2      = (const float*)d_in[14];
    const float* bt2     = (const float*)d_in[15];
    float* out = (float*)d_out;

    __half *pX, *pA1, *pA2;
    cudaGetSymbolAddress((void**)&pX,  g_X);
    cudaGetSymbolAddress((void**)&pA1, g_A1);
    cudaGetSymbolAddress((void**)&pA2, g_A2);

    cudaFuncSetAttribute(gemm_mma<INCH>,  cudaFuncAttributeMaxDynamicSharedMemorySize, GEMM_SMEM);
    cudaFuncSetAttribute(gemm_mma<OUTCH>, cudaFuncAttributeMaxDynamicSharedMemorySize, GEMM_SMEM);

    const dim3 gemm_grid(NTOT / 128, OUTCH / 128);
    const int bn_blocks = (OUTCH * NTOT / 4) / 256;   // 8192

    prep_kernel<<<WSPLIT_BLOCKS + 128, 256>>>(W_fuse, W1, W2, xyz1, xyz2);
    build_input<<<NTOT, 384>>>(points1, points2);

    const int woff_f = 0;
    const int woff_1 = OUTCH * INCH;
    const int woff_2 = OUTCH * INCH + OUTCH * OUTCH;

    // layer fuse
    gemm_mma<INCH><<<gemm_grid, 256, GEMM_SMEM>>>(pX, b_fuse, woff_f, 0);
    bn_act<<<bn_blocks, 256>>>(pA1, g_fuse, bt_fuse, 0);

    // layer 1
    gemm_mma<OUTCH><<<gemm_grid, 256, GEMM_SMEM>>>(pA1, b1, woff_1, 1);
    bn_act<<<bn_blocks, 256>>>(pA2, g1, bt1, 1);

    // layer 2 + residual + output
    gemm_mma<OUTCH><<<gemm_grid, 256, GEMM_SMEM>>>(pA2, b2, woff_2, 2);
    final_k<<<bn_blocks, 256>>>(out, g2, bt2);
}

// round 17
// speedup vs baseline: 1.5538x; 1.0587x over previous
#include <cuda_runtime.h>
#include <cuda_fp16.h>
#include <math.h>
#include <stdint.h>

#define BATCH 8
#define NPTS 4096
#define SPTS 1024
#define D1 128
#define D2 256
#define INCH 384
#define OUTCH 256
#define NTOT (BATCH * NPTS)   // 32768
#define BN_EPS 1e-5f
#define WTOT (OUTCH * INCH + 2 * OUTCH * OUTCH)   // 229376

// ---------------- scratch (device globals; no allocs allowed) ----------------
__device__ __align__(256) __half g_X[(size_t)NTOT * INCH];    // fp16 input, sample-major
__device__ __align__(256) __half g_A1[(size_t)NTOT * OUTCH];  // layer-fuse activation
__device__ __align__(256) __half g_A2[(size_t)NTOT * OUTCH];  // layer-1 activation
__device__ __align__(256) __half g_Z[(size_t)NTOT * OUTCH];   // pre-BN GEMM out (fp16)
__device__ __align__(256) __half g_W[WTOT];                   // fp16 weights (all 3 layers)
__device__ float g_w3[NTOT * 3];
__device__ int   g_i3[NTOT * 3];
__device__ float g_psum[3][OUTCH];   // per-layer BN partial sums (atomics, fp32-exact)
__device__ float g_psq[3][OUTCH];

// ---------------- helpers ----------------
__device__ __forceinline__ uint32_t smem_to_u32(const void* p) {
    uint32_t a;
    asm("{ .reg .u64 t; cvta.to.shared.u64 t, %1; cvt.u32.u64 %0, t; }" : "=r"(a) : "l"(p));
    return a;
}
#define SMZ(o) ((o) ^ (((o) >> 3) & 0x70))   // 128B-row swizzle
#define CP16(dst, src) \
    asm volatile("cp.async.cg.shared.global [%0], [%1], 16;" :: "r"(dst), "l"(src) : "memory")
template <int N>
__device__ __forceinline__ void cp_wait() {
    asm volatile("cp.async.wait_group %0;" :: "n"(N) : "memory");
}
__device__ __forceinline__ void ldsm_x4(uint32_t& r0, uint32_t& r1, uint32_t& r2, uint32_t& r3,
                                        uint32_t addr) {
    asm volatile("ldmatrix.sync.aligned.m8n8.x4.shared.b16 {%0,%1,%2,%3}, [%4];"
                 : "=r"(r0), "=r"(r1), "=r"(r2), "=r"(r3) : "r"(addr));
}
__device__ __forceinline__ void mma_fp16(float& c0, float& c1, float& c2, float& c3,
                                         uint32_t a0, uint32_t a1, uint32_t a2, uint32_t a3,
                                         uint32_t b0, uint32_t b1) {
    asm volatile("mma.sync.aligned.m16n8k16.row.col.f32.f16.f16.f32 "
                 "{%0,%1,%2,%3}, {%4,%5,%6,%7}, {%8,%9}, {%0,%1,%2,%3};"
                 : "+f"(c0), "+f"(c1), "+f"(c2), "+f"(c3)
                 : "r"(a0), "r"(a1), "r"(a2), "r"(a3), "r"(b0), "r"(b1));
}
__device__ __forceinline__ float gelu_exact(float x) {
    return 0.5f * x * (1.0f + erff(x * 0.70710678118654752f));
}

// ---------------- kernel 1: per-sample top-3 neighbors + weights ----------------
__global__ __launch_bounds__(256) void topk_kernel(
    const float* __restrict__ xyz1, const float* __restrict__ xyz2)
{
    __shared__ float4 q[SPTS];
    const int b = blockIdx.y;
    const int n = blockIdx.x * blockDim.x + threadIdx.x;

    for (int s = threadIdx.x; s < SPTS; s += blockDim.x) {
        const float* p = xyz2 + ((size_t)b * SPTS + s) * 3;
        float x = p[0], y = p[1], z = p[2];
        q[s] = make_float4(x, y, z, x * x + y * y + z * z);
    }
    __syncthreads();

    const float* p = xyz1 + ((size_t)b * NPTS + n) * 3;
    float px = p[0], py = p[1], pz = p[2];
    float rn = px * px + py * py + pz * pz;

    float d0 = 3.4e38f, d1 = 3.4e38f, d2 = 3.4e38f;
    int i0 = 0, i1 = 0, i2 = 0;
    #pragma unroll 4
    for (int s = 0; s < SPTS; s++) {
        float4 qq = q[s];
        float d = rn - 2.0f * (px * qq.x + py * qq.y + pz * qq.z) + qq.w;
        if (d < d2) {
            if (d < d1) {
                if (d < d0) { d2 = d1; i2 = i1; d1 = d0; i1 = i0; d0 = d; i0 = s; }
                else        { d2 = d1; i2 = i1; d1 = d;  i1 = s; }
            } else          { d2 = d;  i2 = s; }
        }
    }
    float r0 = 1.0f / (d0 + 1e-8f);
    float r1 = 1.0f / (d1 + 1e-8f);
    float r2 = 1.0f / (d2 + 1e-8f);
    float rs = 1.0f / (r0 + r1 + r2);
    const int sample = b * NPTS + n;
    g_w3[sample * 3 + 0] = r0 * rs;
    g_w3[sample * 3 + 1] = r1 * rs;
    g_w3[sample * 3 + 2] = r2 * rs;
    g_i3[sample * 3 + 0] = i0;
    g_i3[sample * 3 + 1] = i1;
    g_i3[sample * 3 + 2] = i2;
}

// ---------------- kernel 2: build fused input (fp16), sample-major ----------------
__global__ __launch_bounds__(384) void build_input(
    const float* __restrict__ points1, const float* __restrict__ points2)
{
    __shared__ float w[3];
    __shared__ int id[3];
    const int n = blockIdx.x;
    if (threadIdx.x < 3) {
        w[threadIdx.x]  = g_w3[n * 3 + threadIdx.x];
        id[threadIdx.x] = g_i3[n * 3 + threadIdx.x];
    }
    __syncthreads();
    const int c = threadIdx.x;
    float v;
    if (c < D1) {
        v = __ldg(points1 + (size_t)n * D1 + c);
    } else {
        const int b = n >> 12;
        const int cc = c - D1;
        const float* base = points2 + (size_t)b * SPTS * D2 + cc;
        v = w[0] * __ldg(base + (size_t)id[0] * D2)
          + w[1] * __ldg(base + (size_t)id[1] * D2)
          + w[2] * __ldg(base + (size_t)id[2] * D2);
    }
    g_X[(size_t)n * INCH + c] = __float2half_rn(v);
}

// ---------------- kernel 3: weights fp32 -> fp16 + zero stat accumulators ----------------
__global__ __launch_bounds__(256) void wsplit_all(
    const float* __restrict__ Wf, const float* __restrict__ W1, const float* __restrict__ W2)
{
    int i = blockIdx.x * 256 + threadIdx.x;
    if (i < 3 * OUTCH) { (&g_psum[0][0])[i] = 0.0f; (&g_psq[0][0])[i] = 0.0f; }
    if (i >= WTOT) return;
    float w;
    if (i < OUTCH * INCH)                      w = Wf[i];
    else if (i < OUTCH * INCH + OUTCH * OUTCH) w = W1[i - OUTCH * INCH];
    else                                       w = W2[i - OUTCH * INCH - OUTCH * OUTCH];
    g_W[i] = __float2half_rn(w);
}

// ---------------- GEMM: single-pass fp16, BK=64 (R13/R14 structure), fp16 Z out ----------------
// CTA 128x128, BK=64, 3-stage cp.async pipeline, 2 barriers/chunk.
#define STAGE_SZ 32768
#define NSTAGE 3
#define GEMM_SMEM (NSTAGE * STAGE_SZ + 512)

// 128 rows x 64 fp16 (128B/row) tile = 16KB; 4 CP16/thread.
__device__ __forceinline__ void load_tile64(uint32_t dst, const __half* src,
                                            int ldK, int row0, int k0, int tid) {
    #pragma unroll
    for (int j = 0; j < 4; j++) {
        int g = tid + j * 256;
        int r = g >> 3;
        int c16 = (g & 7) * 16;
        const char* s = (const char*)(src + (size_t)(row0 + r) * ldK + k0) + c16;
        CP16(dst + SMZ(r * 128 + c16), s);
    }
}

template <int K>
__global__ __launch_bounds__(256, 2) void gemm_mma(
    const __half* __restrict__ X, const float* __restrict__ bias, int woff, int layer)
{
    constexpr int NC = K / 64;       // chunks (6 or 4)
    extern __shared__ char smem[];
    const uint32_t sb = smem_to_u32(smem);
    const int tid = threadIdx.x;
    const int wid = tid >> 5;
    const int lane = tid & 31;
    const int sample0 = blockIdx.x * 128;
    const int n0 = blockIdx.y * 128;

    const int mWarp = (wid & 1) * 64;
    const int nWarp = (wid >> 1) * 32;

    if (tid < 128) ((float*)(smem + NSTAGE * STAGE_SZ))[tid] = bias[n0 + tid];

    const __half* W = g_W + woff;

    // prologue: chunks 0,1,2 into stages 0,1,2
    #pragma unroll
    for (int i = 0; i < NSTAGE; i++) {
        const uint32_t st = sb + i * STAGE_SZ;
        load_tile64(st,         X, K, sample0, i * 64, tid);
        load_tile64(st + 16384, W, K, n0,      i * 64, tid);
        asm volatile("cp.async.commit_group;" ::: "memory");
    }

    float acc[4][4][4];
    #pragma unroll
    for (int a = 0; a < 4; a++)
        #pragma unroll
        for (int b2 = 0; b2 < 4; b2++)
            #pragma unroll
            for (int c = 0; c < 4; c++) acc[a][b2][c] = 0.0f;

    const int aRow = mWarp + (lane & 15);
    const int aColHalf = (lane >> 4) * 16;             // bytes
    const int bRow = nWarp + ((lane >> 4) << 3) + (lane & 7);
    const int bColHalf = ((lane >> 3) & 1) * 16;       // bytes

    int stage = 0;
    for (int i = 0; i < NC; i++) {
        if (i <= NC - 3)      cp_wait<2>();
        else if (i == NC - 2) cp_wait<1>();
        else                  cp_wait<0>();
        __syncthreads();

        const uint32_t sA = sb + stage * STAGE_SZ;
        const uint32_t sB = sA + 16384;

        #pragma unroll
        for (int k16 = 0; k16 < 4; k16++) {
            uint32_t af[4][4];
            #pragma unroll
            for (int mb = 0; mb < 4; mb++) {
                uint32_t addr = sA + SMZ((aRow + mb * 16) * 128 + k16 * 32 + aColHalf);
                ldsm_x4(af[mb][0], af[mb][1], af[mb][2], af[mb][3], addr);
            }
            uint32_t bf[2][4];
            #pragma unroll
            for (int p = 0; p < 2; p++) {
                uint32_t addr = sB + SMZ((bRow + p * 16) * 128 + k16 * 32 + bColHalf);
                ldsm_x4(bf[p][0], bf[p][1], bf[p][2], bf[p][3], addr);
            }
            #pragma unroll
            for (int mb = 0; mb < 4; mb++)
                #pragma unroll
                for (int nb = 0; nb < 4; nb++) {
                    uint32_t b0 = bf[nb >> 1][(nb & 1) * 2];
                    uint32_t b1 = bf[nb >> 1][(nb & 1) * 2 + 1];
                    mma_fp16(acc[mb][nb][0], acc[mb][nb][1], acc[mb][nb][2], acc[mb][nb][3],
                             af[mb][0], af[mb][1], af[mb][2], af[mb][3], b0, b1);
                }
        }
        __syncthreads();

        if (i + NSTAGE < NC) {
            const int j = i + NSTAGE;
            const uint32_t st = sb + stage * STAGE_SZ;   // (i+3)%3 == i%3
            load_tile64(st,         X, K, sample0, j * 64, tid);
            load_tile64(st + 16384, W, K, n0,      j * 64, tid);
            asm volatile("cp.async.commit_group;" ::: "memory");
        }
        stage = (stage + 1 == NSTAGE) ? 0 : stage + 1;
    }

    // epilogue: bias, write fp16 Z (sample-major), fused fp32-exact BN sums
    const float* sbias = (const float*)(smem + NSTAGE * STAGE_SZ);
    const int rr = lane >> 2;
    const int cc = (lane & 3) * 2;
    #pragma unroll
    for (int nb = 0; nb < 4; nb++) {
        const int col = nWarp + nb * 8 + cc;
        const float b0 = sbias[col], b1 = sbias[col + 1];
        float cs0 = 0.0f, cs1 = 0.0f, cq0 = 0.0f, cq1 = 0.0f;
        #pragma unroll
        for (int mb = 0; mb < 4; mb++) {
            const int row0 = sample0 + mWarp + mb * 16 + rr;
            float v00 = acc[mb][nb][0] + b0;
            float v01 = acc[mb][nb][1] + b1;
            float v10 = acc[mb][nb][2] + b0;
            float v11 = acc[mb][nb][3] + b1;
            __half2 z0 = __floats2half2_rn(v00, v01);
            __half2 z1 = __floats2half2_rn(v10, v11);
            *(__half2*)(g_Z + (size_t)row0 * OUTCH + n0 + col)       = z0;
            *(__half2*)(g_Z + (size_t)(row0 + 8) * OUTCH + n0 + col) = z1;
            cs0 += v00 + v10;
            cs1 += v01 + v11;
            cq0 += v00 * v00 + v10 * v10;
            cq1 += v01 * v01 + v11 * v11;
        }
        #pragma unroll
        for (int off = 4; off <= 16; off <<= 1) {
            cs0 += __shfl_xor_sync(0xFFFFFFFF, cs0, off);
            cs1 += __shfl_xor_sync(0xFFFFFFFF, cs1, off);
            cq0 += __shfl_xor_sync(0xFFFFFFFF, cq0, off);
            cq1 += __shfl_xor_sync(0xFFFFFFFF, cq1, off);
        }
        if (lane < 4) {
            atomicAdd(&g_psum[layer][n0 + col],     cs0);
            atomicAdd(&g_psum[layer][n0 + col + 1], cs1);
            atomicAdd(&g_psq[layer][n0 + col],      cq0);
            atomicAdd(&g_psq[layer][n0 + col + 1],  cq1);
        }
    }
}

// ---------------- BN(+stats finalize) + GELU: fp16 Z -> fp16 activation (8 elem/thread) ----------------
__global__ __launch_bounds__(256) void bn_act(
    __half* __restrict__ A, const float* __restrict__ gamma, const float* __restrict__ beta,
    int layer)
{
    __shared__ float s_sc[OUTCH], s_sh[OUTCH];
    const int t = threadIdx.x;
    {
        float s = g_psum[layer][t];
        float q = g_psq[layer][t];
        float m = s * (1.0f / NTOT);
        float var = q * (1.0f / NTOT) - m * m;
        float r = rsqrtf(var + BN_EPS);
        float sc = r * __ldg(gamma + t);
        s_sc[t] = sc;
        s_sh[t] = __ldg(beta + t) - m * sc;
    }
    __syncthreads();

    const int idx8 = blockIdx.x * 256 + t;       // group of 8 elements
    const int c8 = (idx8 & 31) * 8;              // channel base
    uint4 zv = ((const uint4*)g_Z)[idx8];
    __half2 z[4] = { *reinterpret_cast<__half2*>(&zv.x), *reinterpret_cast<__half2*>(&zv.y),
                     *reinterpret_cast<__half2*>(&zv.z), *reinterpret_cast<__half2*>(&zv.w) };
    uint4 v;
    uint32_t* vp = (uint32_t*)&v;
    #pragma unroll
    for (int j = 0; j < 4; j++) {
        const int c = c8 + j * 2;
        __half2 h;
        h.x = __float2half_rn(gelu_exact(fmaf(__half2float(z[j].x), s_sc[c + 0], s_sh[c + 0])));
        h.y = __float2half_rn(gelu_exact(fmaf(__half2float(z[j].y), s_sc[c + 1], s_sh[c + 1])));
        vp[j] = *reinterpret_cast<uint32_t*>(&h);
    }
    ((uint4*)A)[idx8] = v;
}

// ---------------- final: BN(+stats) + residual + GELU -> fp32 out (8 elem/thread) ----------------
__global__ __launch_bounds__(256) void final_k(
    float* __restrict__ out, const float* __restrict__ gamma, const float* __restrict__ beta)
{
    __shared__ float s_sc[OUTCH], s_sh[OUTCH];
    const int t = threadIdx.x;
    {
        float s = g_psum[2][t];
        float q = g_psq[2][t];
        float m = s * (1.0f / NTOT);
        float var = q * (1.0f / NTOT) - m * m;
        float r = rsqrtf(var + BN_EPS);
        float sc = r * __ldg(gamma + t);
        s_sc[t] = sc;
        s_sh[t] = __ldg(beta + t) - m * sc;
    }
    __syncthreads();

    const int idx8 = blockIdx.x * 256 + t;
    const int c8 = (idx8 & 31) * 8;
    uint4 zv = ((const uint4*)g_Z)[idx8];
    uint4 rv = ((const uint4*)g_A1)[idx8];
    const uint32_t* zp = (const uint32_t*)&zv;
    const uint32_t* rp = (const uint32_t*)&rv;
    float4 o0, o1;
    float* op = (float*)&o0;   // o0.x..o0.w, then o1 via second pointer
    #pragma unroll
    for (int j = 0; j < 4; j++) {
        const int c = c8 + j * 2;
        __half2 zj = *reinterpret_cast<const __half2*>(&zp[j]);
        __half2 rj = *reinterpret_cast<const __half2*>(&rp[j]);
        float a = gelu_exact(fmaf(__half2float(zj.x), s_sc[c + 0], s_sh[c + 0]) + __half2float(rj.x));
        float b = gelu_exact(fmaf(__half2float(zj.y), s_sc[c + 1], s_sh[c + 1]) + __half2float(rj.y));
        if (j < 2) { op[j * 2] = a; op[j * 2 + 1] = b; }
        else { ((float*)&o1)[(j - 2) * 2] = a; ((float*)&o1)[(j - 2) * 2 + 1] = b; }
    }
    ((float4*)out)[idx8 * 2]     = o0;
    ((float4*)out)[idx8 * 2 + 1] = o1;
}

// ---------------- launch ----------------
extern "C" void kernel_launch(void* const* d_in, const int* in_sizes, int n_in,
                              void* d_out, int out_size) {
    const float* xyz1    = (const float*)d_in[0];
    const float* xyz2    = (const float*)d_in[1];
    const float* points1 = (const float*)d_in[2];
    const float* points2 = (const float*)d_in[3];
    const float* W_fuse  = (const float*)d_in[4];
    const float* b_fuse  = (const float*)d_in[5];
    const float* g_fuse  = (const float*)d_in[6];
    const float* bt_fuse = (const float*)d_in[7];
    const float* W1      = (const float*)d_in[8];
    const float* b1      = (const float*)d_in[9];
    const float* g1      = (const float*)d_in[10];
    const float* bt1     = (const float*)d_in[11];
    const float* W2      = (const float*)d_in[12];
    const float* b2      = (const float*)d_in[13];
    const float* g2      = (const float*)d_in[14];
    const float* bt2     = (const float*)d_in[15];
    float* out = (float*)d_out;

    __half *pX, *pA1, *pA2;
    cudaGetSymbolAddress((void**)&pX,  g_X);
    cudaGetSymbolAddress((void**)&pA1, g_A1);
    cudaGetSymbolAddress((void**)&pA2, g_A2);

    cudaFuncSetAttribute(gemm_mma<INCH>,  cudaFuncAttributeMaxDynamicSharedMemorySize, GEMM_SMEM);
    cudaFuncSetAttribute(gemm_mma<OUTCH>, cudaFuncAttributeMaxDynamicSharedMemorySize, GEMM_SMEM);

    const dim3 gemm_grid(NTOT / 128, OUTCH / 128);
    const int bn_blocks = (OUTCH * NTOT / 8) / 256;   // 4096

    wsplit_all<<<(WTOT + 255) / 256, 256>>>(W_fuse, W1, W2);
    topk_kernel<<<dim3(NPTS / 256, BATCH), 256>>>(xyz1, xyz2);
    build_input<<<NTOT, 384>>>(points1, points2);

    const int woff_f = 0;
    const int woff_1 = OUTCH * INCH;
    const int woff_2 = OUTCH * INCH + OUTCH * OUTCH;

    // layer fuse
    gemm_mma<INCH><<<gemm_grid, 256, GEMM_SMEM>>>(pX, b_fuse, woff_f, 0);
    bn_act<<<bn_blocks, 256>>>(pA1, g_fuse, bt_fuse, 0);

    // layer 1
    gemm_mma<OUTCH><<<gemm_grid, 256, GEMM_SMEM>>>(pA1, b1, woff_1, 1);
    bn_act<<<bn_blocks, 256>>>(pA2, g1, bt1, 1);

    // layer 2 + residual + output
    gemm_mma<OUTCH><<<gemm_grid, 256, GEMM_SMEM>>>(pA2, b2, woff_2, 2);
    final_k<<<bn_blocks, 256>>>(out, g2, bt2);
}